// round 11
// baseline (speedup 1.0000x reference)
#include <cuda_runtime.h>
#include <cuda_fp16.h>

#define N_NODES 50000
#define N_REL   1000
#define D       128
#define NNZ_MAX 800000

#define NB       592                      // K1 grid: 4 blocks/SM -> co-resident
#define SCAN_NB  ((N_NODES + 255) / 256)  // 196 scan blocks (subset of NB)
#define Q        64                       // edges per gather warp

// Scratch (allocation-free rule: __device__ globals)
__device__ float g_exp_lr[N_REL];
__device__ float g_coef[N_REL];           // exp/S * 2^112 (magic-convert folded)
__device__ float g_S;
__device__ int   g_cnt[N_NODES];
__device__ int   g_bsum[SCAN_NB];
__device__ int   g_tick1;                 // ticket barrier, NB-wide (2 uses/launch)
__device__ int   g_tick2;                 // ticket barrier, SCAN_NB-wide
__device__ int   g_offs[N_NODES + 1];
__device__ __align__(16) int g_rank[NNZ_MAX];
// 64-bit packed edge: coef_f32_bits<<32 | col<<16 | row
__device__ __align__(16) unsigned long long g_edges[NNZ_MAX];
__device__ __align__(16) __half g_inh[(size_t)N_NODES * D];   // fp16 features

// Monotonic ticket barrier: counter only grows; each use consumes exactly NBLK
// increments, so boundaries stay multiples of NBLK -> graph-replay-safe.
__device__ __forceinline__ void grid_bar(int* tick, int NBLK) {
    __syncthreads();
    __threadfence();
    if (threadIdx.x == 0) {
        const int t = atomicAdd(tick, 1);
        const int target = (t / NBLK + 1) * NBLK;
        while (atomicAdd(tick, 0) < target) {}
    }
    __syncthreads();
}

// ---------------------------------------------------------------------------
// K1: A) zero cnt/S + relation scores (warp/rel; shift=0 safe) + fp16 staging
//     -- bar(592) --
//     B) histogram + per-edge rank + softmax denominator
//     -- bar(592) -- blocks >=196 exit --
//     C) (196 blocks) coef normalize + CSR offset scan
// ---------------------------------------------------------------------------
__global__ void __launch_bounds__(256, 4)
k_prep(const float* __restrict__ inlayer, const float* __restrict__ dual,
       const float* __restrict__ w, const float* __restrict__ b,
       const int* __restrict__ rowp, const int* __restrict__ relp, int nnz) {
    const int tid  = blockIdx.x * blockDim.x + threadIdx.x;
    const int nthr = NB * 256;
    const int lane = threadIdx.x & 31;
    const int t    = threadIdx.x;
    const int bid  = blockIdx.x;
    __shared__ int   sm[256];
    __shared__ float smf[8];

    // ---- Phase A ----
    if (tid == 0) g_S = 0.f;
    for (int i = tid; i < N_NODES; i += nthr) g_cnt[i] = 0;

    const int r = tid >> 5;
    if (r < N_REL) {
        const float4 a  = reinterpret_cast<const float4*>(dual + (size_t)r * D)[lane];
        const float4 ww = reinterpret_cast<const float4*>(w)[lane];
        float s = a.x * ww.x + a.y * ww.y + a.z * ww.z + a.w * ww.w;
#pragma unroll
        for (int o = 16; o > 0; o >>= 1) s += __shfl_xor_sync(0xffffffffu, s, o);
        if (lane == 0) {
            s += b[0];
            const float lr = (s > 0.f) ? s : 0.01f * s;
            g_exp_lr[r] = expf(lr);
        }
    }

    {   // fp16 staging: 1.6M float4 -> uint2 (4 halves)
        const int nv = (N_NODES * D) / 4;
        const float4* in4 = reinterpret_cast<const float4*>(inlayer);
        uint2* out2 = reinterpret_cast<uint2*>(g_inh);
        for (int i = tid; i < nv; i += nthr) {
            const float4 v = __ldg(in4 + i);
            const __half2 h01 = __floats2half2_rn(v.x, v.y);
            const __half2 h23 = __floats2half2_rn(v.z, v.w);
            uint2 p;
            p.x = *reinterpret_cast<const unsigned*>(&h01);
            p.y = *reinterpret_cast<const unsigned*>(&h23);
            out2[i] = p;
        }
    }

    grid_bar(&g_tick1, NB);

    // ---- Phase B ----
    {
        const int nvec = nnz >> 2;
        const int4* row4 = reinterpret_cast<const int4*>(rowp);
        const int4* rel4 = reinterpret_cast<const int4*>(relp);
        int4* rank4 = reinterpret_cast<int4*>(g_rank);

        float s = 0.f;
        for (int i = tid; i < nvec; i += nthr) {
            const int4 r0 = __ldg(row4 + i);
            const int4 q0 = __ldg(rel4 + i);
            int4 rk;
            rk.x = atomicAdd(&g_cnt[r0.x], 1);
            rk.y = atomicAdd(&g_cnt[r0.y], 1);
            rk.z = atomicAdd(&g_cnt[r0.z], 1);
            rk.w = atomicAdd(&g_cnt[r0.w], 1);
            rank4[i] = rk;
            s += g_exp_lr[q0.x] + g_exp_lr[q0.y] + g_exp_lr[q0.z] + g_exp_lr[q0.w];
        }
        const int e0 = (nvec << 2) + tid;
        if (e0 < nnz) {
            g_rank[e0] = atomicAdd(&g_cnt[__ldg(rowp + e0)], 1);
            s += g_exp_lr[__ldg(relp + e0)];
        }
#pragma unroll
        for (int o = 16; o > 0; o >>= 1) s += __shfl_xor_sync(0xffffffffu, s, o);
        if ((t & 31) == 0) smf[t >> 5] = s;
        __syncthreads();
        if (t < 32) {
            float v = (t < 8) ? smf[t] : 0.f;
#pragma unroll
            for (int o = 4; o > 0; o >>= 1) v += __shfl_xor_sync(0xffffffffu, v, o);
            if (t == 0) atomicAdd(&g_S, v);
        }
    }

    grid_bar(&g_tick1, NB);
    if (bid >= SCAN_NB) return;          // free 396 blocks' SMs

    // ---- Phase C: coef table + offset scan (196 blocks) ----
    if (bid == 0) {
        const float invS112 = 5.192296858534828e33f / __ldcg(&g_S);  // 2^112/S
        for (int rr = t; rr < N_REL; rr += 256) g_coef[rr] = g_exp_lr[rr] * invS112;
        if (t == 0) g_offs[N_NODES] = nnz;
    }

    const int gid = bid * 256 + t;
    const int v = (gid < N_NODES) ? __ldcg(&g_cnt[gid]) : 0;
    sm[t] = v;
    __syncthreads();
#pragma unroll
    for (int o = 1; o < 256; o <<= 1) {
        const int p = (t >= o) ? sm[t - o] : 0;
        __syncthreads();
        sm[t] += p;
        __syncthreads();
    }
    const int incl = sm[t];
    if (t == 255) g_bsum[bid] = incl;

    grid_bar(&g_tick2, SCAN_NB);

    sm[t] = (t < bid) ? __ldcg(&g_bsum[t]) : 0;
    __syncthreads();
#pragma unroll
    for (int o = 128; o > 0; o >>= 1) {
        if (t < o) sm[t] += sm[t + o];
        __syncthreads();
    }
    const int base = sm[0];
    if (gid < N_NODES) g_offs[gid] = base + incl - v;
}

// ---------------------------------------------------------------------------
// K2: reorder into 64-bit packed edges (coef folded in; no atomics:
// pos = offs[row] + rank), 8 edges/thread. Also pre-zeroes output rows that
// the balanced gather will hit with atomics (quota-boundary / empty rows).
// ---------------------------------------------------------------------------
__global__ void __launch_bounds__(256)
k_reorder(const int* __restrict__ rowp, const int* __restrict__ colp,
          const int* __restrict__ relp, int nnz, float* __restrict__ out) {
    const int nvec = nnz >> 2;
    const int tid  = blockIdx.x * blockDim.x + threadIdx.x;
    const int lane = threadIdx.x & 31;

#pragma unroll
    for (int k = 0; k < 2; k++) {
        const int i = tid * 2 + k;
        if (i < nvec) {
            const int4 r  = __ldg(reinterpret_cast<const int4*>(rowp) + i);
            const int4 c  = __ldg(reinterpret_cast<const int4*>(colp) + i);
            const int4 q  = __ldg(reinterpret_cast<const int4*>(relp) + i);
            const int4 rk = __ldg(reinterpret_cast<const int4*>(g_rank) + i);
            const int p0 = __ldg(&g_offs[r.x]) + rk.x;
            const int p1 = __ldg(&g_offs[r.y]) + rk.y;
            const int p2 = __ldg(&g_offs[r.z]) + rk.z;
            const int p3 = __ldg(&g_offs[r.w]) + rk.w;
            const unsigned cf0 = __float_as_uint(__ldg(&g_coef[q.x]));
            const unsigned cf1 = __float_as_uint(__ldg(&g_coef[q.y]));
            const unsigned cf2 = __float_as_uint(__ldg(&g_coef[q.z]));
            const unsigned cf3 = __float_as_uint(__ldg(&g_coef[q.w]));
            g_edges[p0] = ((unsigned long long)cf0 << 32) | ((unsigned)c.x << 16) | (unsigned)r.x;
            g_edges[p1] = ((unsigned long long)cf1 << 32) | ((unsigned)c.y << 16) | (unsigned)r.y;
            g_edges[p2] = ((unsigned long long)cf2 << 32) | ((unsigned)c.z << 16) | (unsigned)r.z;
            g_edges[p3] = ((unsigned long long)cf3 << 32) | ((unsigned)c.w << 16) | (unsigned)r.w;
        }
    }
    const int e = (nvec << 2) + tid;
    if (e < nnz) {
        const int row = __ldg(rowp + e);
        const int pos = __ldg(&g_offs[row]) + g_rank[e];
        const unsigned cf = __float_as_uint(__ldg(&g_coef[__ldg(relp + e)]));
        g_edges[pos] = ((unsigned long long)cf << 32) |
                       ((unsigned)__ldg(colp + e) << 16) | (unsigned)row;
    }

    // pre-zero atomic-candidate rows (warp-strided; lane stores one float4)
    const int wglob  = (blockIdx.x * blockDim.x + threadIdx.x) >> 5;
    const int nwarps = (gridDim.x * blockDim.x) >> 5;
    for (int rrow = wglob; rrow < N_NODES; rrow += nwarps) {
        const int s = __ldg(&g_offs[rrow]);
        const int en = __ldg(&g_offs[rrow + 1]);
        const bool flag = (s == en) || (s % Q == 0) || (en % Q == 0) ||
                          (en == nnz) || ((s / Q) != ((en - 1) / Q));
        if (flag)
            reinterpret_cast<float4*>(out + (size_t)rrow * D)[lane] =
                make_float4(0.f, 0.f, 0.f, 0.f);
    }
}

// ---------------------------------------------------------------------------
// K3: edge-balanced gather over fp16 features. Warp owns Q consecutive CSR
// edges; coef comes from the edge word (no table); magic-shift convert
// (no F2F): f32(h) = as_float(((h&0x7FFF)<<13)|(sign<<16)) * 2^112, with
// 2^112 folded into coef. Interior rows -> float4 store; quota-boundary
// rows -> RED.v4 into pre-zeroed output.
// ---------------------------------------------------------------------------
__device__ __forceinline__ void acc_h2(unsigned p, float cp, float& a, float& b) {
    const unsigned u0 = ((p << 13) & 0x0FFFE000u) | ((p << 16) & 0x80000000u);
    const unsigned u1 = ((p >> 3) & 0x0FFFE000u) | (p & 0x80000000u);
    a += cp * __uint_as_float(u0);
    b += cp * __uint_as_float(u1);
}

__device__ __forceinline__ void flush_row(float* __restrict__ out, int row,
                                          const float4& a, bool atomic, int lane) {
    float* p = out + (size_t)row * D + lane * 4;
    if (atomic) {
        asm volatile("red.global.add.v4.f32 [%0], {%1, %2, %3, %4};"
                     :: "l"(p), "f"(a.x), "f"(a.y), "f"(a.z), "f"(a.w)
                     : "memory");
    } else {
        *reinterpret_cast<float4*>(p) = a;
    }
}

__global__ void __launch_bounds__(128)
k_gather(float* __restrict__ out, int nnz) {
    const int lane = threadIdx.x & 31;
    const int wid  = (blockIdx.x * blockDim.x + threadIdx.x) >> 5;
    const int base = wid * Q;
    if (base >= nnz) return;
    const int end = min(base + Q, nnz);

    unsigned long long ed = __ldg(&g_edges[base]);
    uint2 v = __ldg(reinterpret_cast<const uint2*>(
                        g_inh + (size_t)((unsigned)(ed >> 16) & 0xFFFFu) * D) + lane);
    int currow = (int)((unsigned)ed & 0xFFFFu);
    bool first = true;
    float4 acc = make_float4(0.f, 0.f, 0.f, 0.f);

    for (int i = base + 1; i <= end; i++) {
        // prefetch next edge + feature (independent of flush logic)
        unsigned long long edn = 0;
        uint2 vn = make_uint2(0u, 0u);
        if (i < end) {
            edn = __ldg(&g_edges[i]);
            vn = __ldg(reinterpret_cast<const uint2*>(
                           g_inh + (size_t)((unsigned)(edn >> 16) & 0xFFFFu) * D) + lane);
        }
        // process current edge
        const int row = (int)((unsigned)ed & 0xFFFFu);
        if (row != currow) {
            flush_row(out, currow, acc, first, lane);   // first segment: atomic
            first = false;
            acc = make_float4(0.f, 0.f, 0.f, 0.f);
            currow = row;
        }
        const float c = __uint_as_float((unsigned)(ed >> 32));  // coef*2^112
        acc_h2(v.x, c, acc.x, acc.y);
        acc_h2(v.y, c, acc.z, acc.w);
        ed = edn; v = vn;
    }
    flush_row(out, currow, acc, true, lane);            // last segment: atomic
}

// ---------------------------------------------------------------------------
// kernel_launch
// Inputs: 0 inlayer [N,D] f32 | 1 dual [R,D] f32 | 2 conv_w [D] f32
//         3 conv_b [1] f32    | 4 edge_idx [2,NNZ] i32 | 5 edge_rel [NNZ] i32
// Output: [N, D] f32
// ---------------------------------------------------------------------------
extern "C" void kernel_launch(void* const* d_in, const int* in_sizes, int n_in,
                              void* d_out, int out_size) {
    const float* inlayer = (const float*)d_in[0];
    const float* dual    = (const float*)d_in[1];
    const float* conv_w  = (const float*)d_in[2];
    const float* conv_b  = (const float*)d_in[3];
    const int*   eidx    = (const int*)d_in[4];
    const int*   erel    = (const int*)d_in[5];
    float*       out     = (float*)d_out;

    const int nnz = in_sizes[5];
    const int* rowp = eidx;
    const int* colp = eidx + nnz;

    k_prep<<<NB, 256>>>(inlayer, dual, conv_w, conv_b, rowp, erel, nnz);
    k_reorder<<<(nnz / 8 + 255) / 256, 256>>>(rowp, colp, erel, nnz, out);

    const int nwarps = (nnz + Q - 1) / Q;                 // 12500
    k_gather<<<(nwarps * 32 + 127) / 128, 128>>>(out, nnz);
}

// round 12
// speedup vs baseline: 1.1109x; 1.1109x over previous
#include <cuda_runtime.h>
#include <cuda_fp16.h>

#define N_NODES 50000
#define N_REL   1000
#define D       128
#define NNZ_MAX 800000

#define FUSE_NB  592          // fused kernel: 4 blocks/SM -> co-resident
#define SCAN_BLK 512
#define SCAN_NB  ((N_NODES + SCAN_BLK - 1) / SCAN_BLK)   // 98 co-resident blocks
#define Q        64           // edges per gather warp

// Scratch (allocation-free rule: __device__ globals)
__device__ float g_exp_lr[N_REL];
__device__ float g_coef[N_REL];           // exp/S * 2^112 (magic-convert folded)
__device__ float g_S;
__device__ int   g_cnt[N_NODES];
__device__ int   g_bsum[SCAN_NB];
__device__ int   g_tick1;                 // ticket barrier (fused, 592-wide)
__device__ int   g_tick2;                 // ticket barrier (scan, 98-wide)
__device__ int   g_offs[N_NODES + 1];
__device__ __align__(16) int g_rank[NNZ_MAX];
// 64-bit packed edge: coef_f32_bits<<32 | col<<16 | row
__device__ __align__(16) unsigned long long g_edges[NNZ_MAX];
__device__ __align__(16) __half g_inh[(size_t)N_NODES * D];   // fp16 features

// Monotonic ticket barrier: counter only grows; each use consumes exactly NBLK
// increments, so boundaries stay multiples of NBLK -> graph-replay-safe.
__device__ __forceinline__ void grid_bar(int* tick, int NBLK) {
    __syncthreads();
    __threadfence();
    if (threadIdx.x == 0) {
        const int t = atomicAdd(tick, 1);
        const int target = (t / NBLK + 1) * NBLK;
        while (atomicAdd(tick, 0) < target) {}
    }
    __syncthreads();
}

// ---------------------------------------------------------------------------
// K1 (fused): phase A: zero cnt/S + relation scores (warp/rel; shift=0 safe
//             by softmax shift-invariance with O(1) inputs)
//             -- bar(592) --
//             phase B: hist+rank+denominator, THEN fp16 staging in the same
//             phase (bandwidth stream overlaps atomic latency across warps).
// ---------------------------------------------------------------------------
__global__ void __launch_bounds__(256, 4)
k_fused(const float* __restrict__ inlayer, const float* __restrict__ dual,
        const float* __restrict__ w, const float* __restrict__ b,
        const int* __restrict__ rowp, const int* __restrict__ relp, int nnz) {
    const int tid  = blockIdx.x * blockDim.x + threadIdx.x;
    const int nthr = FUSE_NB * 256;
    const int lane = threadIdx.x & 31;

    // ---- phase A ----
    if (tid == 0) g_S = 0.f;
    for (int i = tid; i < N_NODES; i += nthr) g_cnt[i] = 0;

    const int r = tid >> 5;
    if (r < N_REL) {
        const float4 a  = reinterpret_cast<const float4*>(dual + (size_t)r * D)[lane];
        const float4 ww = reinterpret_cast<const float4*>(w)[lane];
        float s = a.x * ww.x + a.y * ww.y + a.z * ww.z + a.w * ww.w;
#pragma unroll
        for (int o = 16; o > 0; o >>= 1) s += __shfl_xor_sync(0xffffffffu, s, o);
        if (lane == 0) {
            s += b[0];
            const float lr = (s > 0.f) ? s : 0.01f * s;
            g_exp_lr[r] = expf(lr);
        }
    }

    grid_bar(&g_tick1, FUSE_NB);

    // ---- phase B: histogram + rank + denominator ----
    const int nvec = nnz >> 2;
    {
        const int4* row4 = reinterpret_cast<const int4*>(rowp);
        const int4* rel4 = reinterpret_cast<const int4*>(relp);
        int4* rank4 = reinterpret_cast<int4*>(g_rank);

        float s = 0.f;
        for (int i = tid; i < nvec; i += nthr) {
            const int4 r0 = __ldg(row4 + i);
            const int4 q0 = __ldg(rel4 + i);
            int4 rk;
            rk.x = atomicAdd(&g_cnt[r0.x], 1);
            rk.y = atomicAdd(&g_cnt[r0.y], 1);
            rk.z = atomicAdd(&g_cnt[r0.z], 1);
            rk.w = atomicAdd(&g_cnt[r0.w], 1);
            rank4[i] = rk;
            s += g_exp_lr[q0.x] + g_exp_lr[q0.y] + g_exp_lr[q0.z] + g_exp_lr[q0.w];
        }
        const int e0 = (nvec << 2) + tid;
        if (e0 < nnz) {
            g_rank[e0] = atomicAdd(&g_cnt[__ldg(rowp + e0)], 1);
            s += g_exp_lr[__ldg(relp + e0)];
        }
#pragma unroll
        for (int o = 16; o > 0; o >>= 1) s += __shfl_xor_sync(0xffffffffu, s, o);
        __shared__ float smf[8];
        if ((threadIdx.x & 31) == 0) smf[threadIdx.x >> 5] = s;
        __syncthreads();
        if (threadIdx.x < 32) {
            float v = (threadIdx.x < 8) ? smf[threadIdx.x] : 0.f;
#pragma unroll
            for (int o = 4; o > 0; o >>= 1) v += __shfl_xor_sync(0xffffffffu, v, o);
            if (threadIdx.x == 0) atomicAdd(&g_S, v);
        }
    }

    // ---- phase B (cont.): fp16 staging, overlapped across warps with hist ----
    {
        const int nv = (N_NODES * D) / 4;
        const float4* in4 = reinterpret_cast<const float4*>(inlayer);
        uint2* out2 = reinterpret_cast<uint2*>(g_inh);
        for (int i = tid; i < nv; i += nthr) {
            const float4 v = __ldg(in4 + i);
            const __half2 h01 = __floats2half2_rn(v.x, v.y);
            const __half2 h23 = __floats2half2_rn(v.z, v.w);
            uint2 p;
            p.x = *reinterpret_cast<const unsigned*>(&h01);
            p.y = *reinterpret_cast<const unsigned*>(&h23);
            out2[i] = p;
        }
    }
}

// ---------------------------------------------------------------------------
// K2: scan (98 co-resident blocks, monotonic barrier). Block 0 normalizes the
// coef table with 2^112 folded in (gather's magic fp16 convert scale).
// ---------------------------------------------------------------------------
__global__ void __launch_bounds__(SCAN_BLK)
k_scan(int nnz) {
    __shared__ int sm[SCAN_BLK];
    const int t   = threadIdx.x;
    const int bid = blockIdx.x;
    const int gid = bid * SCAN_BLK + t;

    if (bid == 0) {
        const float invS112 = 5.192296858534828e33f / g_S;   // 2^112 / S
        for (int r = t; r < N_REL; r += SCAN_BLK) g_coef[r] = g_exp_lr[r] * invS112;
    }

    const int v = (gid < N_NODES) ? g_cnt[gid] : 0;
    sm[t] = v;
    __syncthreads();
#pragma unroll
    for (int o = 1; o < SCAN_BLK; o <<= 1) {
        const int p = (t >= o) ? sm[t - o] : 0;
        __syncthreads();
        sm[t] += p;
        __syncthreads();
    }
    const int incl = sm[t];
    if (t == SCAN_BLK - 1) g_bsum[bid] = incl;

    grid_bar(&g_tick2, SCAN_NB);

    sm[t] = (t < bid) ? g_bsum[t] : 0;
    __syncthreads();
#pragma unroll
    for (int o = SCAN_BLK / 2; o > 0; o >>= 1) {
        if (t < o) sm[t] += sm[t + o];
        __syncthreads();
    }
    const int base = sm[0];

    if (gid < N_NODES) g_offs[gid] = base + incl - v;
    if (gid == N_NODES - 1) g_offs[N_NODES] = nnz;
}

// ---------------------------------------------------------------------------
// K3: reorder into 64-bit packed edges (coef folded; pos = offs[row] + rank,
// no atomics), 8 edges/thread. Also pre-zeroes output rows the balanced
// gather will hit with atomics (quota-boundary / empty rows).
// ---------------------------------------------------------------------------
__global__ void __launch_bounds__(256)
k_reorder(const int* __restrict__ rowp, const int* __restrict__ colp,
          const int* __restrict__ relp, int nnz, float* __restrict__ out) {
    const int nvec = nnz >> 2;
    const int tid  = blockIdx.x * blockDim.x + threadIdx.x;
    const int lane = threadIdx.x & 31;

#pragma unroll
    for (int k = 0; k < 2; k++) {
        const int i = tid * 2 + k;
        if (i < nvec) {
            const int4 r  = __ldg(reinterpret_cast<const int4*>(rowp) + i);
            const int4 c  = __ldg(reinterpret_cast<const int4*>(colp) + i);
            const int4 q  = __ldg(reinterpret_cast<const int4*>(relp) + i);
            const int4 rk = __ldg(reinterpret_cast<const int4*>(g_rank) + i);
            const int p0 = __ldg(&g_offs[r.x]) + rk.x;
            const int p1 = __ldg(&g_offs[r.y]) + rk.y;
            const int p2 = __ldg(&g_offs[r.z]) + rk.z;
            const int p3 = __ldg(&g_offs[r.w]) + rk.w;
            const unsigned cf0 = __float_as_uint(__ldg(&g_coef[q.x]));
            const unsigned cf1 = __float_as_uint(__ldg(&g_coef[q.y]));
            const unsigned cf2 = __float_as_uint(__ldg(&g_coef[q.z]));
            const unsigned cf3 = __float_as_uint(__ldg(&g_coef[q.w]));
            g_edges[p0] = ((unsigned long long)cf0 << 32) | ((unsigned)c.x << 16) | (unsigned)r.x;
            g_edges[p1] = ((unsigned long long)cf1 << 32) | ((unsigned)c.y << 16) | (unsigned)r.y;
            g_edges[p2] = ((unsigned long long)cf2 << 32) | ((unsigned)c.z << 16) | (unsigned)r.z;
            g_edges[p3] = ((unsigned long long)cf3 << 32) | ((unsigned)c.w << 16) | (unsigned)r.w;
        }
    }
    const int e = (nvec << 2) + tid;
    if (e < nnz) {
        const int row = __ldg(rowp + e);
        const int pos = __ldg(&g_offs[row]) + g_rank[e];
        const unsigned cf = __float_as_uint(__ldg(&g_coef[__ldg(relp + e)]));
        g_edges[pos] = ((unsigned long long)cf << 32) |
                       ((unsigned)__ldg(colp + e) << 16) | (unsigned)row;
    }

    // pre-zero atomic-candidate rows (warp-strided; lane stores one float4)
    const int wglob  = (blockIdx.x * blockDim.x + threadIdx.x) >> 5;
    const int nwarps = (gridDim.x * blockDim.x) >> 5;
    for (int rrow = wglob; rrow < N_NODES; rrow += nwarps) {
        const int s  = __ldg(&g_offs[rrow]);
        const int en = __ldg(&g_offs[rrow + 1]);
        const bool flag = (s == en) || (s % Q == 0) || (en % Q == 0) ||
                          (en == nnz) || ((s / Q) != ((en - 1) / Q));
        if (flag)
            reinterpret_cast<float4*>(out + (size_t)rrow * D)[lane] =
                make_float4(0.f, 0.f, 0.f, 0.f);
    }
}

// ---------------------------------------------------------------------------
// K4: balanced gather, 4-edge chunks. Warp owns Q=64 consecutive CSR edges.
// Per chunk: 2x ulonglong2 edge loads (16B-aligned) + 4 independent uint2
// feature loads in flight, then sequential accumulate/flush. Magic convert:
// f32(h) = as_float(((h&0x7FFF)<<13)|(sign<<16)) * 2^112 (2^112 in coef).
// Interior rows -> float4 store; boundary rows -> RED.v4 (pre-zeroed).
// ---------------------------------------------------------------------------
__device__ __forceinline__ void acc_h2(unsigned p, float cp, float& a, float& b) {
    const unsigned u0 = ((p << 13) & 0x0FFFE000u) | ((p << 16) & 0x80000000u);
    const unsigned u1 = ((p >> 3) & 0x0FFFE000u) | (p & 0x80000000u);
    a += cp * __uint_as_float(u0);
    b += cp * __uint_as_float(u1);
}

__device__ __forceinline__ void flush_row(float* __restrict__ out, int row,
                                          const float4& a, bool atomic, int lane) {
    float* p = out + (size_t)row * D + lane * 4;
    if (atomic) {
        asm volatile("red.global.add.v4.f32 [%0], {%1, %2, %3, %4};"
                     :: "l"(p), "f"(a.x), "f"(a.y), "f"(a.z), "f"(a.w)
                     : "memory");
    } else {
        *reinterpret_cast<float4*>(p) = a;
    }
}

__global__ void __launch_bounds__(128)
k_gather(float* __restrict__ out, int nnz) {
    const int lane = threadIdx.x & 31;
    const int wid  = (blockIdx.x * blockDim.x + threadIdx.x) >> 5;
    const int base = wid * Q;
    if (base >= nnz) return;
    const int end = min(base + Q, nnz);

    int   currow = (int)((unsigned)__ldg(&g_edges[base]) & 0xFFFFu);
    bool  first  = true;
    float4 acc   = make_float4(0.f, 0.f, 0.f, 0.f);

    int i = base;
    for (; i + 3 < end; i += 4) {
        // batched edge loads (g_edges 16B-aligned; base is Q-aligned)
        const ulonglong2 ea = __ldg(reinterpret_cast<const ulonglong2*>(g_edges + i));
        const ulonglong2 eb = __ldg(reinterpret_cast<const ulonglong2*>(g_edges + i + 2));
        // 4 independent feature loads in flight
        const uint2 v0 = __ldg(reinterpret_cast<const uint2*>(
                g_inh + (size_t)((unsigned)(ea.x >> 16) & 0xFFFFu) * D) + lane);
        const uint2 v1 = __ldg(reinterpret_cast<const uint2*>(
                g_inh + (size_t)((unsigned)(ea.y >> 16) & 0xFFFFu) * D) + lane);
        const uint2 v2 = __ldg(reinterpret_cast<const uint2*>(
                g_inh + (size_t)((unsigned)(eb.x >> 16) & 0xFFFFu) * D) + lane);
        const uint2 v3 = __ldg(reinterpret_cast<const uint2*>(
                g_inh + (size_t)((unsigned)(eb.y >> 16) & 0xFFFFu) * D) + lane);

        const unsigned long long eds[4] = {ea.x, ea.y, eb.x, eb.y};
        const uint2 vs[4] = {v0, v1, v2, v3};
#pragma unroll
        for (int k = 0; k < 4; k++) {
            const int row = (int)((unsigned)eds[k] & 0xFFFFu);
            if (row != currow) {
                flush_row(out, currow, acc, first, lane);
                first = false;
                acc = make_float4(0.f, 0.f, 0.f, 0.f);
                currow = row;
            }
            const float c = __uint_as_float((unsigned)(eds[k] >> 32));
            acc_h2(vs[k].x, c, acc.x, acc.y);
            acc_h2(vs[k].y, c, acc.z, acc.w);
        }
    }
    for (; i < end; i++) {      // tail (only if nnz % 4 != 0 within last quota)
        const unsigned long long ed = __ldg(&g_edges[i]);
        const int row = (int)((unsigned)ed & 0xFFFFu);
        if (row != currow) {
            flush_row(out, currow, acc, first, lane);
            first = false;
            acc = make_float4(0.f, 0.f, 0.f, 0.f);
            currow = row;
        }
        const uint2 v = __ldg(reinterpret_cast<const uint2*>(
                g_inh + (size_t)((unsigned)(ed >> 16) & 0xFFFFu) * D) + lane);
        const float c = __uint_as_float((unsigned)(ed >> 32));
        acc_h2(v.x, c, acc.x, acc.y);
        acc_h2(v.y, c, acc.z, acc.w);
    }
    flush_row(out, currow, acc, true, lane);   // last segment: atomic
}

// ---------------------------------------------------------------------------
// kernel_launch
// Inputs: 0 inlayer [N,D] f32 | 1 dual [R,D] f32 | 2 conv_w [D] f32
//         3 conv_b [1] f32    | 4 edge_idx [2,NNZ] i32 | 5 edge_rel [NNZ] i32
// Output: [N, D] f32
// ---------------------------------------------------------------------------
extern "C" void kernel_launch(void* const* d_in, const int* in_sizes, int n_in,
                              void* d_out, int out_size) {
    const float* inlayer = (const float*)d_in[0];
    const float* dual    = (const float*)d_in[1];
    const float* conv_w  = (const float*)d_in[2];
    const float* conv_b  = (const float*)d_in[3];
    const int*   eidx    = (const int*)d_in[4];
    const int*   erel    = (const int*)d_in[5];
    float*       out     = (float*)d_out;

    const int nnz = in_sizes[5];
    const int* rowp = eidx;
    const int* colp = eidx + nnz;

    k_fused<<<FUSE_NB, 256>>>(inlayer, dual, conv_w, conv_b, rowp, erel, nnz);
    k_scan<<<SCAN_NB, SCAN_BLK>>>(nnz);
    k_reorder<<<(nnz / 8 + 255) / 256, 256>>>(rowp, colp, erel, nnz, out);

    const int nwarps = (nnz + Q - 1) / Q;                 // 12500
    k_gather<<<(nwarps * 32 + 127) / 128, 128>>>(out, nnz);
}

// round 13
// speedup vs baseline: 1.2690x; 1.1422x over previous
#include <cuda_runtime.h>
#include <cuda_fp16.h>

#define N_NODES 50000
#define N_REL   1000
#define D       128
#define NNZ_MAX 800000

#define FUSE_NB  592          // fused kernel: 4 blocks/SM -> co-resident
#define SCAN_BLK 512
#define SCAN_NB  ((N_NODES + SCAN_BLK - 1) / SCAN_BLK)   // 98 co-resident blocks
#define Q        64           // edges per gather warp

// Scratch (allocation-free rule: __device__ globals)
__device__ float g_exp_lr[N_REL];
__device__ float g_coef[N_REL];           // exp / S
__device__ float g_S;
__device__ int   g_cnt[N_NODES];
__device__ int   g_bsum[SCAN_NB];
__device__ int   g_tick1;                 // ticket barrier (fused, 592-wide)
__device__ int   g_tick2;                 // ticket barrier (scan, 98-wide)
__device__ int   g_offs[N_NODES + 1];
__device__ __align__(16) int g_rank[NNZ_MAX];
// 64-bit packed edge: coef_f32_bits<<32 | col<<16 | row
__device__ __align__(16) unsigned long long g_edges[NNZ_MAX];
__device__ __align__(16) __half g_inh[(size_t)N_NODES * D];   // fp16 features

// Monotonic ticket barrier: counter only grows; each use consumes exactly NBLK
// increments, so boundaries stay multiples of NBLK -> graph-replay-safe.
__device__ __forceinline__ void grid_bar(int* tick, int NBLK) {
    __syncthreads();
    __threadfence();
    if (threadIdx.x == 0) {
        const int t = atomicAdd(tick, 1);
        const int target = (t / NBLK + 1) * NBLK;
        while (atomicAdd(tick, 0) < target) {}
    }
    __syncthreads();
}

// ---------------------------------------------------------------------------
// K1 (fused): phase A: zero cnt/S + relation scores (warp/rel; shift=0 safe
//             by softmax shift-invariance with O(1) inputs)
//             -- bar(592) --
//             phase B: hist+rank+denominator, then fp16 staging (bandwidth
//             stream overlaps atomic latency across warps).
// ---------------------------------------------------------------------------
__global__ void __launch_bounds__(256, 4)
k_fused(const float* __restrict__ inlayer, const float* __restrict__ dual,
        const float* __restrict__ w, const float* __restrict__ b,
        const int* __restrict__ rowp, const int* __restrict__ relp, int nnz) {
    const int tid  = blockIdx.x * blockDim.x + threadIdx.x;
    const int nthr = FUSE_NB * 256;
    const int lane = threadIdx.x & 31;

    // ---- phase A ----
    if (tid == 0) g_S = 0.f;
    for (int i = tid; i < N_NODES; i += nthr) g_cnt[i] = 0;

    const int r = tid >> 5;
    if (r < N_REL) {
        const float4 a  = reinterpret_cast<const float4*>(dual + (size_t)r * D)[lane];
        const float4 ww = reinterpret_cast<const float4*>(w)[lane];
        float s = a.x * ww.x + a.y * ww.y + a.z * ww.z + a.w * ww.w;
#pragma unroll
        for (int o = 16; o > 0; o >>= 1) s += __shfl_xor_sync(0xffffffffu, s, o);
        if (lane == 0) {
            s += b[0];
            const float lr = (s > 0.f) ? s : 0.01f * s;
            g_exp_lr[r] = expf(lr);
        }
    }

    grid_bar(&g_tick1, FUSE_NB);

    // ---- phase B: histogram + rank + denominator ----
    const int nvec = nnz >> 2;
    {
        const int4* row4 = reinterpret_cast<const int4*>(rowp);
        const int4* rel4 = reinterpret_cast<const int4*>(relp);
        int4* rank4 = reinterpret_cast<int4*>(g_rank);

        float s = 0.f;
        for (int i = tid; i < nvec; i += nthr) {
            const int4 r0 = __ldg(row4 + i);
            const int4 q0 = __ldg(rel4 + i);
            int4 rk;
            rk.x = atomicAdd(&g_cnt[r0.x], 1);
            rk.y = atomicAdd(&g_cnt[r0.y], 1);
            rk.z = atomicAdd(&g_cnt[r0.z], 1);
            rk.w = atomicAdd(&g_cnt[r0.w], 1);
            rank4[i] = rk;
            s += g_exp_lr[q0.x] + g_exp_lr[q0.y] + g_exp_lr[q0.z] + g_exp_lr[q0.w];
        }
        const int e0 = (nvec << 2) + tid;
        if (e0 < nnz) {
            g_rank[e0] = atomicAdd(&g_cnt[__ldg(rowp + e0)], 1);
            s += g_exp_lr[__ldg(relp + e0)];
        }
#pragma unroll
        for (int o = 16; o > 0; o >>= 1) s += __shfl_xor_sync(0xffffffffu, s, o);
        __shared__ float smf[8];
        if ((threadIdx.x & 31) == 0) smf[threadIdx.x >> 5] = s;
        __syncthreads();
        if (threadIdx.x < 32) {
            float v = (threadIdx.x < 8) ? smf[threadIdx.x] : 0.f;
#pragma unroll
            for (int o = 4; o > 0; o >>= 1) v += __shfl_xor_sync(0xffffffffu, v, o);
            if (threadIdx.x == 0) atomicAdd(&g_S, v);
        }
    }

    // ---- phase B (cont.): fp16 staging ----
    {
        const int nv = (N_NODES * D) / 4;
        const float4* in4 = reinterpret_cast<const float4*>(inlayer);
        uint2* out2 = reinterpret_cast<uint2*>(g_inh);
        for (int i = tid; i < nv; i += nthr) {
            const float4 v = __ldg(in4 + i);
            const __half2 h01 = __floats2half2_rn(v.x, v.y);
            const __half2 h23 = __floats2half2_rn(v.z, v.w);
            uint2 p;
            p.x = *reinterpret_cast<const unsigned*>(&h01);
            p.y = *reinterpret_cast<const unsigned*>(&h23);
            out2[i] = p;
        }
    }
}

// ---------------------------------------------------------------------------
// K2: scan (98 co-resident blocks, monotonic barrier). Block 0 normalizes the
// coef table (plain 1/S — gather uses real F2F converts now).
// ---------------------------------------------------------------------------
__global__ void __launch_bounds__(SCAN_BLK)
k_scan(int nnz) {
    __shared__ int sm[SCAN_BLK];
    const int t   = threadIdx.x;
    const int bid = blockIdx.x;
    const int gid = bid * SCAN_BLK + t;

    if (bid == 0) {
        const float invS = 1.0f / g_S;
        for (int r = t; r < N_REL; r += SCAN_BLK) g_coef[r] = g_exp_lr[r] * invS;
    }

    const int v = (gid < N_NODES) ? g_cnt[gid] : 0;
    sm[t] = v;
    __syncthreads();
#pragma unroll
    for (int o = 1; o < SCAN_BLK; o <<= 1) {
        const int p = (t >= o) ? sm[t - o] : 0;
        __syncthreads();
        sm[t] += p;
        __syncthreads();
    }
    const int incl = sm[t];
    if (t == SCAN_BLK - 1) g_bsum[bid] = incl;

    grid_bar(&g_tick2, SCAN_NB);

    sm[t] = (t < bid) ? g_bsum[t] : 0;
    __syncthreads();
#pragma unroll
    for (int o = SCAN_BLK / 2; o > 0; o >>= 1) {
        if (t < o) sm[t] += sm[t + o];
        __syncthreads();
    }
    const int base = sm[0];

    if (gid < N_NODES) g_offs[gid] = base + incl - v;
    if (gid == N_NODES - 1) g_offs[N_NODES] = nnz;
}

// ---------------------------------------------------------------------------
// K3: reorder into 64-bit packed edges (coef folded; pos = offs[row] + rank,
// no atomics), 8 edges/thread. Also pre-zeroes output rows the balanced
// gather will hit with atomics (quota-boundary / empty rows).
// ---------------------------------------------------------------------------
__global__ void __launch_bounds__(256)
k_reorder(const int* __restrict__ rowp, const int* __restrict__ colp,
          const int* __restrict__ relp, int nnz, float* __restrict__ out) {
    const int nvec = nnz >> 2;
    const int tid  = blockIdx.x * blockDim.x + threadIdx.x;
    const int lane = threadIdx.x & 31;

#pragma unroll
    for (int k = 0; k < 2; k++) {
        const int i = tid * 2 + k;
        if (i < nvec) {
            const int4 r  = __ldg(reinterpret_cast<const int4*>(rowp) + i);
            const int4 c  = __ldg(reinterpret_cast<const int4*>(colp) + i);
            const int4 q  = __ldg(reinterpret_cast<const int4*>(relp) + i);
            const int4 rk = __ldg(reinterpret_cast<const int4*>(g_rank) + i);
            const int p0 = __ldg(&g_offs[r.x]) + rk.x;
            const int p1 = __ldg(&g_offs[r.y]) + rk.y;
            const int p2 = __ldg(&g_offs[r.z]) + rk.z;
            const int p3 = __ldg(&g_offs[r.w]) + rk.w;
            const unsigned cf0 = __float_as_uint(__ldg(&g_coef[q.x]));
            const unsigned cf1 = __float_as_uint(__ldg(&g_coef[q.y]));
            const unsigned cf2 = __float_as_uint(__ldg(&g_coef[q.z]));
            const unsigned cf3 = __float_as_uint(__ldg(&g_coef[q.w]));
            g_edges[p0] = ((unsigned long long)cf0 << 32) | ((unsigned)c.x << 16) | (unsigned)r.x;
            g_edges[p1] = ((unsigned long long)cf1 << 32) | ((unsigned)c.y << 16) | (unsigned)r.y;
            g_edges[p2] = ((unsigned long long)cf2 << 32) | ((unsigned)c.z << 16) | (unsigned)r.z;
            g_edges[p3] = ((unsigned long long)cf3 << 32) | ((unsigned)c.w << 16) | (unsigned)r.w;
        }
    }
    const int e = (nvec << 2) + tid;
    if (e < nnz) {
        const int row = __ldg(rowp + e);
        const int pos = __ldg(&g_offs[row]) + g_rank[e];
        const unsigned cf = __float_as_uint(__ldg(&g_coef[__ldg(relp + e)]));
        g_edges[pos] = ((unsigned long long)cf << 32) |
                       ((unsigned)__ldg(colp + e) << 16) | (unsigned)row;
    }

    // pre-zero atomic-candidate rows (warp-strided; lane stores one float4)
    const int wglob  = (blockIdx.x * blockDim.x + threadIdx.x) >> 5;
    const int nwarps = (gridDim.x * blockDim.x) >> 5;
    for (int rrow = wglob; rrow < N_NODES; rrow += nwarps) {
        const int s  = __ldg(&g_offs[rrow]);
        const int en = __ldg(&g_offs[rrow + 1]);
        const bool flag = (s == en) || (s % Q == 0) || (en % Q == 0) ||
                          (en == nnz) || ((s / Q) != ((en - 1) / Q));
        if (flag)
            reinterpret_cast<float4*>(out + (size_t)rrow * D)[lane] =
                make_float4(0.f, 0.f, 0.f, 0.f);
    }
}

// ---------------------------------------------------------------------------
// K4: balanced gather, 4-edge chunks. Warp owns Q=64 consecutive CSR edges.
// fp16 -> fp32 via F2F converts (__half22float2) on the convert pipe — the
// ALU pipe (R12's bottleneck at 59.8%) keeps only indexing/flush logic.
// Interior rows -> float4 store; boundary rows -> RED.v4 (pre-zeroed).
// ---------------------------------------------------------------------------
__device__ __forceinline__ void acc_edge_cvt(uint2 hv, float c, float4& a) {
    const float2 f01 = __half22float2(*reinterpret_cast<const __half2*>(&hv.x));
    const float2 f23 = __half22float2(*reinterpret_cast<const __half2*>(&hv.y));
    a.x = fmaf(c, f01.x, a.x);
    a.y = fmaf(c, f01.y, a.y);
    a.z = fmaf(c, f23.x, a.z);
    a.w = fmaf(c, f23.y, a.w);
}

__device__ __forceinline__ void flush_row(float* __restrict__ out, int row,
                                          const float4& a, bool atomic, int lane) {
    float* p = out + (size_t)row * D + lane * 4;
    if (atomic) {
        asm volatile("red.global.add.v4.f32 [%0], {%1, %2, %3, %4};"
                     :: "l"(p), "f"(a.x), "f"(a.y), "f"(a.z), "f"(a.w)
                     : "memory");
    } else {
        *reinterpret_cast<float4*>(p) = a;
    }
}

__global__ void __launch_bounds__(128)
k_gather(float* __restrict__ out, int nnz) {
    const int lane = threadIdx.x & 31;
    const int wid  = (blockIdx.x * blockDim.x + threadIdx.x) >> 5;
    const int base = wid * Q;
    if (base >= nnz) return;
    const int end = min(base + Q, nnz);

    int   currow = (int)((unsigned)__ldg(&g_edges[base]) & 0xFFFFu);
    bool  first  = true;
    float4 acc   = make_float4(0.f, 0.f, 0.f, 0.f);

    int i = base;
    for (; i + 3 < end; i += 4) {
        const ulonglong2 ea = __ldg(reinterpret_cast<const ulonglong2*>(g_edges + i));
        const ulonglong2 eb = __ldg(reinterpret_cast<const ulonglong2*>(g_edges + i + 2));
        const uint2 v0 = __ldg(reinterpret_cast<const uint2*>(
                g_inh + (size_t)((unsigned)(ea.x >> 16) & 0xFFFFu) * D) + lane);
        const uint2 v1 = __ldg(reinterpret_cast<const uint2*>(
                g_inh + (size_t)((unsigned)(ea.y >> 16) & 0xFFFFu) * D) + lane);
        const uint2 v2 = __ldg(reinterpret_cast<const uint2*>(
                g_inh + (size_t)((unsigned)(eb.x >> 16) & 0xFFFFu) * D) + lane);
        const uint2 v3 = __ldg(reinterpret_cast<const uint2*>(
                g_inh + (size_t)((unsigned)(eb.y >> 16) & 0xFFFFu) * D) + lane);

        const unsigned long long eds[4] = {ea.x, ea.y, eb.x, eb.y};
        const uint2 vs[4] = {v0, v1, v2, v3};
#pragma unroll
        for (int k = 0; k < 4; k++) {
            const int row = (int)((unsigned)eds[k] & 0xFFFFu);
            if (row != currow) {
                flush_row(out, currow, acc, first, lane);
                first = false;
                acc = make_float4(0.f, 0.f, 0.f, 0.f);
                currow = row;
            }
            const float c = __uint_as_float((unsigned)(eds[k] >> 32));
            acc_edge_cvt(vs[k], c, acc);
        }
    }
    for (; i < end; i++) {
        const unsigned long long ed = __ldg(&g_edges[i]);
        const int row = (int)((unsigned)ed & 0xFFFFu);
        if (row != currow) {
            flush_row(out, currow, acc, first, lane);
            first = false;
            acc = make_float4(0.f, 0.f, 0.f, 0.f);
            currow = row;
        }
        const uint2 v = __ldg(reinterpret_cast<const uint2*>(
                g_inh + (size_t)((unsigned)(ed >> 16) & 0xFFFFu) * D) + lane);
        const float c = __uint_as_float((unsigned)(ed >> 32));
        acc_edge_cvt(v, c, acc);
    }
    flush_row(out, currow, acc, true, lane);   // last segment: atomic
}

// ---------------------------------------------------------------------------
// kernel_launch
// Inputs: 0 inlayer [N,D] f32 | 1 dual [R,D] f32 | 2 conv_w [D] f32
//         3 conv_b [1] f32    | 4 edge_idx [2,NNZ] i32 | 5 edge_rel [NNZ] i32
// Output: [N, D] f32
// ---------------------------------------------------------------------------
extern "C" void kernel_launch(void* const* d_in, const int* in_sizes, int n_in,
                              void* d_out, int out_size) {
    const float* inlayer = (const float*)d_in[0];
    const float* dual    = (const float*)d_in[1];
    const float* conv_w  = (const float*)d_in[2];
    const float* conv_b  = (const float*)d_in[3];
    const int*   eidx    = (const int*)d_in[4];
    const int*   erel    = (const int*)d_in[5];
    float*       out     = (float*)d_out;

    const int nnz = in_sizes[5];
    const int* rowp = eidx;
    const int* colp = eidx + nnz;

    k_fused<<<FUSE_NB, 256>>>(inlayer, dual, conv_w, conv_b, rowp, erel, nnz);
    k_scan<<<SCAN_NB, SCAN_BLK>>>(nnz);
    k_reorder<<<(nnz / 8 + 255) / 256, 256>>>(rowp, colp, erel, nnz, out);

    const int nwarps = (nnz + Q - 1) / Q;                 // 12500
    k_gather<<<(nwarps * 32 + 127) / 128, 128>>>(out, nnz);
}